// round 2
// baseline (speedup 1.0000x reference)
#include <cuda_runtime.h>

// Problem constants
#define BB 4
#define TT 4096
#define CC 1024
#define HH 128

// Scratch for projected Q, K, V (8 MB each) — __device__ globals, no allocation.
__device__ float g_Q[BB * TT * HH];
__device__ float g_K[BB * TT * HH];
__device__ float g_V[BB * TT * HH];

// ---------------------------------------------------------------------------
// Projection GEMM: X[16384, 1024] @ W[1024, 128] -> O[16384, 128]
// BM=64, BN=128 (full H), BK=16. 256 threads, 4x8 micro-tile per thread.
// X tile stored k-transposed in smem so inner loop reads are conflict-free.
// blockIdx.y in {0,1,2} selects (Wq->g_Q), (Wk->g_K), (Wv->g_V).
// ---------------------------------------------------------------------------
__global__ __launch_bounds__(256) void proj_kernel(
    const float* __restrict__ X,
    const float* __restrict__ Wq,
    const float* __restrict__ Wk,
    const float* __restrict__ Wv)
{
    __shared__ float sX[16][68];    // [k][m], padded stride 68
    __shared__ float sW[16][128];   // [k][n]

    const int mt = blockIdx.x;
    const float* W;
    float* O;
    if (blockIdx.y == 0)      { W = Wq; O = g_Q; }
    else if (blockIdx.y == 1) { W = Wk; O = g_K; }
    else                      { W = Wv; O = g_V; }

    const int tid = threadIdx.x;
    const int tr = tid >> 4;        // 0..15 -> rows 4*tr..4*tr+3
    const int tc = tid & 15;        // 0..15 -> cols 8*tc..8*tc+7

    const int lr = tid >> 2;        // 0..63  (X-tile row)
    const int lk = (tid & 3) << 2;  // 0,4,8,12 (X-tile k offset)

    const float* Xbase = X + (size_t)mt * 64 * CC;

    float acc[4][8];
    #pragma unroll
    for (int i = 0; i < 4; ++i)
        #pragma unroll
        for (int j = 0; j < 8; ++j) acc[i][j] = 0.f;

    for (int k0 = 0; k0 < CC; k0 += 16) {
        // Stage loads to registers
        float4 x4 = *(const float4*)(Xbase + (size_t)lr * CC + k0 + lk);
        const int i0 = tid, i1 = tid + 256;   // 512 float4s of W tile
        float4 w0 = *(const float4*)(W + (size_t)(k0 + (i0 >> 5)) * HH + ((i0 & 31) << 2));
        float4 w1 = *(const float4*)(W + (size_t)(k0 + (i1 >> 5)) * HH + ((i1 & 31) << 2));

        __syncthreads();  // previous iteration's reads done
        sX[lk + 0][lr] = x4.x;
        sX[lk + 1][lr] = x4.y;
        sX[lk + 2][lr] = x4.z;
        sX[lk + 3][lr] = x4.w;
        *(float4*)&sW[i0 >> 5][(i0 & 31) << 2] = w0;
        *(float4*)&sW[i1 >> 5][(i1 & 31) << 2] = w1;
        __syncthreads();

        #pragma unroll
        for (int kk = 0; kk < 16; ++kk) {
            float4 a  = *(float4*)&sX[kk][4 * tr];
            float4 b0 = *(float4*)&sW[kk][8 * tc];
            float4 b1 = *(float4*)&sW[kk][8 * tc + 4];
            float av[4] = {a.x, a.y, a.z, a.w};
            float bv[8] = {b0.x, b0.y, b0.z, b0.w, b1.x, b1.y, b1.z, b1.w};
            #pragma unroll
            for (int i = 0; i < 4; ++i)
                #pragma unroll
                for (int j = 0; j < 8; ++j)
                    acc[i][j] = fmaf(av[i], bv[j], acc[i][j]);
        }
    }

    float* Ob = O + (size_t)mt * 64 * HH;
    #pragma unroll
    for (int i = 0; i < 4; ++i) {
        float4 o0 = {acc[i][0], acc[i][1], acc[i][2], acc[i][3]};
        float4 o1 = {acc[i][4], acc[i][5], acc[i][6], acc[i][7]};
        *(float4*)&Ob[(4 * tr + i) * HH + 8 * tc]     = o0;
        *(float4*)&Ob[(4 * tr + i) * HH + 8 * tc + 4] = o1;
    }
}

// ---------------------------------------------------------------------------
// Causal attention (flash style), scores[t,s] = k[t]·q[s] / 32, s <= t.
// Tile: 64 t-rows x 64 s-cols, D=128. 512 threads (32x16 thread grid),
// each thread owns 2 rows x 4 cols of S and 2 rows x 8 cols of O.
// Load balancing: block handles q-tiles {p, 63-p} -> exactly 65 s-tiles each.
// Grid: (32 pairs, 4 batches) = 128 blocks = one balanced wave.
// ---------------------------------------------------------------------------
__global__ __launch_bounds__(512) void attn_kernel(float* __restrict__ out)
{
    extern __shared__ float sm[];
    float* Kt = sm;                      // [128][68] transposed k-tile ("rows")
    float* Qt = Kt + 128 * 68;           // [128][68] transposed q-tile ("cols")
    float* sV = Qt + 128 * 68;           // [64][128] v-tile, row-major
    float* sP = sV + 64 * 128;           // [64][68]  probabilities

    const int b    = blockIdx.y;
    const int pair = blockIdx.x;         // 0..31
    const int tid  = threadIdx.x;
    const int tr   = tid >> 4;           // 0..31 -> rows 2*tr, 2*tr+1
    const int tc   = tid & 15;           // 0..15 -> cols 4*tc..4*tc+3

    const int ldr = tid >> 3;            // 0..63  (transpose-load row)
    const int ldh = (tid & 7) << 2;      // 0..28  (transpose-load h offset)

    const int row0 = 2 * tr;             // this thread's S/O row pair
    const int col0 = 4 * tc;             // this thread's S col quad
    const int oc0  = 8 * tc;             // this thread's O col octet

    for (int half = 0; half < 2; ++half) {
        const int it = (half == 0) ? (63 - pair) : pair;   // q-tile index

        __syncthreads();  // previous half's smem reads complete
        // Load K tile (the score ROWS) transposed: Kt[h][r] = k[b, it*64+r, h]
        {
            const float* src = g_K + ((size_t)(b * TT) + it * 64) * HH;
            #pragma unroll
            for (int h0 = 0; h0 < 128; h0 += 32) {
                float4 v = *(const float4*)(src + (size_t)ldr * HH + h0 + ldh);
                const int h = h0 + ldh;
                Kt[(h + 0) * 68 + ldr] = v.x;
                Kt[(h + 1) * 68 + ldr] = v.y;
                Kt[(h + 2) * 68 + ldr] = v.z;
                Kt[(h + 3) * 68 + ldr] = v.w;
            }
        }

        float m[2] = {-1e30f, -1e30f};
        float l[2] = {0.f, 0.f};
        float O[2][8];
        #pragma unroll
        for (int i = 0; i < 2; ++i)
            #pragma unroll
            for (int j = 0; j < 8; ++j) O[i][j] = 0.f;

        for (int j = 0; j <= it; ++j) {
            __syncthreads();  // previous PV reads of Qt/sV done (also orders Kt)
            // Load Q tile (score COLS) transposed + V tile row-major
            {
                const float* qsrc = g_Q + ((size_t)(b * TT) + j * 64) * HH;
                #pragma unroll
                for (int h0 = 0; h0 < 128; h0 += 32) {
                    float4 v = *(const float4*)(qsrc + (size_t)ldr * HH + h0 + ldh);
                    const int h = h0 + ldh;
                    Qt[(h + 0) * 68 + ldr] = v.x;
                    Qt[(h + 1) * 68 + ldr] = v.y;
                    Qt[(h + 2) * 68 + ldr] = v.z;
                    Qt[(h + 3) * 68 + ldr] = v.w;
                }
                const float* vsrc = g_V + ((size_t)(b * TT) + j * 64) * HH;
                int f4 = tid;
                #pragma unroll
                for (int v4 = 0; v4 < 4; ++v4, f4 += 512) {
                    const int vr = f4 >> 5;
                    const int vh = (f4 & 31) << 2;
                    *(float4*)&sV[vr * 128 + vh] =
                        *(const float4*)(vsrc + (size_t)vr * HH + vh);
                }
            }
            __syncthreads();

            // S[2][4] = Kt rows (row0..) dot Qt cols (col0..)
            float S[2][4];
            #pragma unroll
            for (int i = 0; i < 2; ++i)
                #pragma unroll
                for (int jj = 0; jj < 4; ++jj) S[i][jj] = 0.f;

            #pragma unroll 8
            for (int kk = 0; kk < 128; ++kk) {
                float2 a = *(float2*)&Kt[kk * 68 + row0];
                float4 q = *(float4*)&Qt[kk * 68 + col0];
                S[0][0] = fmaf(a.x, q.x, S[0][0]);
                S[0][1] = fmaf(a.x, q.y, S[0][1]);
                S[0][2] = fmaf(a.x, q.z, S[0][2]);
                S[0][3] = fmaf(a.x, q.w, S[0][3]);
                S[1][0] = fmaf(a.y, q.x, S[1][0]);
                S[1][1] = fmaf(a.y, q.y, S[1][1]);
                S[1][2] = fmaf(a.y, q.z, S[1][2]);
                S[1][3] = fmaf(a.y, q.w, S[1][3]);
            }

            // scale + causal mask (only diagonal tile is partial)
            const bool diag = (j == it);
            #pragma unroll
            for (int i = 0; i < 2; ++i)
                #pragma unroll
                for (int jj = 0; jj < 4; ++jj) {
                    float v = S[i][jj] * 0.03125f;   // C^-0.5 = 1/32
                    if (diag && (col0 + jj > row0 + i)) v = -1e30f;
                    S[i][jj] = v;
                }

            // online softmax per row (16 threads share a row; xor<16 stays in group)
            #pragma unroll
            for (int i = 0; i < 2; ++i) {
                float rmax = fmaxf(fmaxf(S[i][0], S[i][1]), fmaxf(S[i][2], S[i][3]));
                #pragma unroll
                for (int off = 8; off >= 1; off >>= 1)
                    rmax = fmaxf(rmax, __shfl_xor_sync(0xffffffffu, rmax, off));
                const float mnew = fmaxf(m[i], rmax);
                const float corr = __expf(m[i] - mnew);
                float rsum = 0.f;
                #pragma unroll
                for (int jj = 0; jj < 4; ++jj) {
                    S[i][jj] = __expf(S[i][jj] - mnew);
                    rsum += S[i][jj];
                }
                #pragma unroll
                for (int off = 8; off >= 1; off >>= 1)
                    rsum += __shfl_xor_sync(0xffffffffu, rsum, off);
                l[i] = l[i] * corr + rsum;
                m[i] = mnew;
                #pragma unroll
                for (int jj = 0; jj < 8; ++jj) O[i][jj] *= corr;
                float4 p4 = {S[i][0], S[i][1], S[i][2], S[i][3]};
                *(float4*)&sP[(row0 + i) * 68 + col0] = p4;
            }
            __syncthreads();  // sP visible to all tc of each row group

            // O += P @ V
            const float* __restrict__ pr0 = &sP[(row0 + 0) * 68];
            const float* __restrict__ pr1 = &sP[(row0 + 1) * 68];
            #pragma unroll 4
            for (int c = 0; c < 64; ++c) {
                const float p0 = pr0[c];
                const float p1 = pr1[c];
                float4 v0 = *(const float4*)&sV[c * 128 + oc0];
                float4 v1 = *(const float4*)&sV[c * 128 + oc0 + 4];
                O[0][0] = fmaf(p0, v0.x, O[0][0]);
                O[0][1] = fmaf(p0, v0.y, O[0][1]);
                O[0][2] = fmaf(p0, v0.z, O[0][2]);
                O[0][3] = fmaf(p0, v0.w, O[0][3]);
                O[0][4] = fmaf(p0, v1.x, O[0][4]);
                O[0][5] = fmaf(p0, v1.y, O[0][5]);
                O[0][6] = fmaf(p0, v1.z, O[0][6]);
                O[0][7] = fmaf(p0, v1.w, O[0][7]);
                O[1][0] = fmaf(p1, v0.x, O[1][0]);
                O[1][1] = fmaf(p1, v0.y, O[1][1]);
                O[1][2] = fmaf(p1, v0.z, O[1][2]);
                O[1][3] = fmaf(p1, v0.w, O[1][3]);
                O[1][4] = fmaf(p1, v1.x, O[1][4]);
                O[1][5] = fmaf(p1, v1.y, O[1][5]);
                O[1][6] = fmaf(p1, v1.z, O[1][6]);
                O[1][7] = fmaf(p1, v1.w, O[1][7]);
            }
        }

        // Normalize and write output rows of this q-tile
        float* ob = out + ((size_t)(b * TT) + it * 64) * HH;
        #pragma unroll
        for (int i = 0; i < 2; ++i) {
            const float linv = 1.f / l[i];
            float4 o0 = {O[i][0] * linv, O[i][1] * linv, O[i][2] * linv, O[i][3] * linv};
            float4 o1 = {O[i][4] * linv, O[i][5] * linv, O[i][6] * linv, O[i][7] * linv};
            *(float4*)&ob[(2 * tr + i) * HH + oc0]     = o0;
            *(float4*)&ob[(2 * tr + i) * HH + oc0 + 4] = o1;
        }
    }
}

// ---------------------------------------------------------------------------
// Launch
// ---------------------------------------------------------------------------
extern "C" void kernel_launch(void* const* d_in, const int* in_sizes, int n_in,
                              void* d_out, int out_size)
{
    const float* ix = (const float*)d_in[0];
    const float* Wq = (const float*)d_in[1];
    const float* Wk = (const float*)d_in[2];
    const float* Wv = (const float*)d_in[3];
    float* out = (float*)d_out;

    // QKV projection: 256 M-tiles x {q,k,v}
    proj_kernel<<<dim3(256, 3), 256>>>(ix, Wq, Wk, Wv);

    // Attention: 32 balanced tile-pairs x 4 batches, 117 KB dynamic smem
    const size_t shmem = (size_t)(128 * 68 * 2 + 64 * 128 + 64 * 68) * sizeof(float);
    cudaFuncSetAttribute(attn_kernel, cudaFuncAttributeMaxDynamicSharedMemorySize,
                         (int)shmem);
    attn_kernel<<<dim3(32, 4), 512, shmem>>>(out);
}

// round 5
// speedup vs baseline: 1.2228x; 1.2228x over previous
#include <cuda_runtime.h>
#include <cuda_bf16.h>
#include <cstdint>

// Problem constants
#define BB 4
#define TT 4096
#define CC 1024
#define HH 128

// ---------------------------------------------------------------------------
// Device scratch (no allocations allowed)
// ---------------------------------------------------------------------------
__device__ float g_Q[BB * TT * HH];
__device__ float g_K[BB * TT * HH];
__device__ float g_V[BB * TT * HH];
__device__ __nv_bfloat16 g_Ahi[BB * TT * CC];       // ix split-hi  [16384][1024]
__device__ __nv_bfloat16 g_Alo[BB * TT * CC];       // ix split-lo
__device__ __nv_bfloat16 g_Bhi[3 * HH * CC];        // W^T split-hi [3][128][1024]
__device__ __nv_bfloat16 g_Blo[3 * HH * CC];        // W^T split-lo

// ---------------------------------------------------------------------------
// Helpers (baseline sm_100 PTX only: ldmatrix + mma.sync — NO tcgen05)
// ---------------------------------------------------------------------------
__device__ __forceinline__ uint32_t smem_u32(const void* p) {
    uint32_t a;
    asm("{ .reg .u64 t; cvta.to.shared.u64 t, %1; cvt.u32.u64 %0, t; }"
        : "=r"(a) : "l"(p));
    return a;
}

#define LDMX4(r, addr) \
    asm volatile("ldmatrix.sync.aligned.m8n8.x4.shared.b16 {%0,%1,%2,%3}, [%4];" \
        : "=r"((r)[0]), "=r"((r)[1]), "=r"((r)[2]), "=r"((r)[3]) : "r"(addr))

#define MMA_BF16(c, a, b0, b1) \
    asm volatile("mma.sync.aligned.m16n8k16.row.col.f32.bf16.bf16.f32 " \
        "{%0,%1,%2,%3}, {%4,%5,%6,%7}, {%8,%9}, {%0,%1,%2,%3};" \
        : "+f"((c)[0]), "+f"((c)[1]), "+f"((c)[2]), "+f"((c)[3]) \
        : "r"((a)[0]), "r"((a)[1]), "r"((a)[2]), "r"((a)[3]), "r"(b0), "r"(b1))

__device__ __forceinline__ uint32_t pack_bf2(__nv_bfloat16 a, __nv_bfloat16 b) {
    return (uint32_t)__bfloat16_as_ushort(a) |
           ((uint32_t)__bfloat16_as_ushort(b) << 16);
}

// ---------------------------------------------------------------------------
// Split ix -> (hi, lo) bf16. 16.8M elems, 4/thread. Memory-bound.
// ---------------------------------------------------------------------------
__global__ __launch_bounds__(256) void convert_a(const float* __restrict__ x)
{
    const size_t base = ((size_t)blockIdx.x * 256 + threadIdx.x) * 4;
    float4 v = *(const float4*)(x + base);
    __nv_bfloat16 h0 = __float2bfloat16(v.x), h1 = __float2bfloat16(v.y);
    __nv_bfloat16 h2 = __float2bfloat16(v.z), h3 = __float2bfloat16(v.w);
    __nv_bfloat16 l0 = __float2bfloat16(v.x - __bfloat162float(h0));
    __nv_bfloat16 l1 = __float2bfloat16(v.y - __bfloat162float(h1));
    __nv_bfloat16 l2 = __float2bfloat16(v.z - __bfloat162float(h2));
    __nv_bfloat16 l3 = __float2bfloat16(v.w - __bfloat162float(h3));
    uint2 ph = {pack_bf2(h0, h1), pack_bf2(h2, h3)};
    uint2 pl = {pack_bf2(l0, l1), pack_bf2(l2, l3)};
    *(uint2*)&g_Ahi[base] = ph;
    *(uint2*)&g_Alo[base] = pl;
}

// ---------------------------------------------------------------------------
// Transpose + split W [1024,128] -> W^T [128,1024] bf16 hi/lo.
// ---------------------------------------------------------------------------
__global__ __launch_bounds__(256) void transpose_w(
    const float* __restrict__ Wq, const float* __restrict__ Wk,
    const float* __restrict__ Wv)
{
    const int w = blockIdx.y;
    const float* src = (w == 0) ? Wq : (w == 1) ? Wk : Wv;
    const int idx = blockIdx.x * 256 + threadIdx.x;   // 0..131071
    const int n = idx >> 10;
    const int k = idx & 1023;
    const float v = src[(size_t)k * HH + n];
    __nv_bfloat16 h = __float2bfloat16(v);
    __nv_bfloat16 l = __float2bfloat16(v - __bfloat162float(h));
    g_Bhi[(size_t)w * HH * CC + idx] = h;
    g_Blo[(size_t)w * HH * CC + idx] = l;
}

// ---------------------------------------------------------------------------
// HMMA projection GEMM: D[128,128] = A[128,1024] @ B^T, split-bf16 (3 passes).
// 256 threads = 8 warps; warp w owns m-rows 16w..16w+15, all 128 n.
// K staged 32 (double-buffered smem, padded stride 40 elems -> ldmatrix
// conflict-free). mma.sync.m16n8k16 bf16 with fp32 accumulators.
// grid = (128 M-tiles, 3 weights).
// ---------------------------------------------------------------------------
#define PADK       40                     // 32 k elems + 8 pad (80B row stride)
#define TILE_BYTES (128 * PADK * 2)       // 10240 B per [128][32] tile
#define BUF_BYTES  (4 * TILE_BYTES)       // Ahi|Alo|Bhi|Blo = 40960 B
#define GEMM_SMEM  (2 * BUF_BYTES)        // double-buffered = 81920 B

__global__ __launch_bounds__(256) void gemm_proj()
{
    extern __shared__ __align__(16) char smem[];
    const uint32_t sb = smem_u32(smem);
    const int tid  = threadIdx.x;
    const int w    = tid >> 5;
    const int lane = tid & 31;
    const int mt   = blockIdx.x;
    const int wt   = blockIdx.y;

    const __nv_bfloat16* Ah = g_Ahi;
    const __nv_bfloat16* Al = g_Alo;
    const __nv_bfloat16* Bh = g_Bhi + (size_t)wt * HH * CC;
    const __nv_bfloat16* Bl = g_Blo + (size_t)wt * HH * CC;
    float* Out = (wt == 0) ? g_Q : (wt == 1) ? g_K : g_V;

    const size_t arow0 = (size_t)mt * 128;

    float acc[16][4];
    #pragma unroll
    for (int i = 0; i < 16; ++i)
        #pragma unroll
        for (int j = 0; j < 4; ++j) acc[i][j] = 0.f;

    // Stage loader: [128 rows][32 k] bf16 for each of Ahi/Alo/Bhi/Blo.
    auto ld_stage = [&](int s) {
        const uint32_t buf = (uint32_t)(s & 1) * BUF_BYTES;
        const int k0 = s * 32;
        #pragma unroll
        for (int h = 0; h < 2; ++h) {
            const int c   = tid + h * 256;     // 0..511
            const int row = c >> 2;
            const int ke  = (c & 3) * 8;       // 8 elems = 16B
            const uint32_t so = buf + (uint32_t)(row * PADK + ke) * 2;
            *(uint4*)(smem + so)                  = *(const uint4*)(Ah + (arow0 + row) * CC + k0 + ke);
            *(uint4*)(smem + so + TILE_BYTES)     = *(const uint4*)(Al + (arow0 + row) * CC + k0 + ke);
            *(uint4*)(smem + so + 2 * TILE_BYTES) = *(const uint4*)(Bh + (size_t)row * CC + k0 + ke);
            *(uint4*)(smem + so + 3 * TILE_BYTES) = *(const uint4*)(Bl + (size_t)row * CC + k0 + ke);
        }
    };

    // ldmatrix per-lane addressing: lanes 0-15 -> rows r0..r15 col 0,
    // lanes 16-31 -> rows r0..r15 col 8 (canonical x4 fragment order).
    const int lrow  = lane & 15;
    const int lcol8 = (lane >> 4) * 8;

    ld_stage(0);
    __syncthreads();

    for (int s = 0; s < 32; ++s) {
        if (s + 1 < 32) ld_stage(s + 1);   // fill other buffer (overlaps compute)
        const uint32_t buf = sb + (uint32_t)(s & 1) * BUF_BYTES;
        #pragma unroll
        for (int kk = 0; kk < 32; kk += 16) {
            const uint32_t aaddr =
                buf + (uint32_t)((16 * w + lrow) * PADK + kk + lcol8) * 2;
            uint32_t ah[4], al[4];
            LDMX4(ah, aaddr);
            LDMX4(al, aaddr + TILE_BYTES);
            #pragma unroll
            for (int j = 0; j < 8; ++j) {
                const uint32_t baddr = buf + 2 * TILE_BYTES +
                    (uint32_t)((16 * j + lrow) * PADK + kk + lcol8) * 2;
                uint32_t bh[4], bl[4];
                LDMX4(bh, baddr);
                LDMX4(bl, baddr + TILE_BYTES);
                // n-tile 2j:   B frag {r0, r2};  n-tile 2j+1: {r1, r3}
                MMA_BF16(acc[2 * j],     ah, bh[0], bh[2]);
                MMA_BF16(acc[2 * j],     ah, bl[0], bl[2]);
                MMA_BF16(acc[2 * j],     al, bh[0], bh[2]);
                MMA_BF16(acc[2 * j + 1], ah, bh[1], bh[3]);
                MMA_BF16(acc[2 * j + 1], ah, bl[1], bl[3]);
                MMA_BF16(acc[2 * j + 1], al, bh[1], bh[3]);
            }
        }
        __syncthreads();
    }

    // Epilogue: c0,c1 -> row m0, cols n0,n0+1; c2,c3 -> row m0+8.
    const int m0 = 16 * w + (lane >> 2);
    const int nc = (lane & 3) * 2;
    #pragma unroll
    for (int nt = 0; nt < 16; ++nt) {
        float2 lo = {acc[nt][0], acc[nt][1]};
        float2 hi = {acc[nt][2], acc[nt][3]};
        *(float2*)&Out[(arow0 + m0)     * HH + nt * 8 + nc] = lo;
        *(float2*)&Out[(arow0 + m0 + 8) * HH + nt * 8 + nc] = hi;
    }
}

// ---------------------------------------------------------------------------
// Causal attention (unchanged, proven): scores[t,s] = k[t]·q[s] / 32, s <= t.
// ---------------------------------------------------------------------------
__global__ __launch_bounds__(512) void attn_kernel(float* __restrict__ out)
{
    extern __shared__ float sm[];
    float* Kt = sm;                      // [128][68] transposed k-tile ("rows")
    float* Qt = Kt + 128 * 68;           // [128][68] transposed q-tile ("cols")
    float* sV = Qt + 128 * 68;           // [64][128] v-tile, row-major
    float* sP = sV + 64 * 128;           // [64][68]  probabilities

    const int b    = blockIdx.y;
    const int pair = blockIdx.x;         // 0..31
    const int tid  = threadIdx.x;
    const int tr   = tid >> 4;           // 0..31 -> rows 2*tr, 2*tr+1
    const int tc   = tid & 15;           // 0..15 -> cols 4*tc..4*tc+3

    const int ldr = tid >> 3;            // 0..63  (transpose-load row)
    const int ldh = (tid & 7) << 2;      // 0..28  (transpose-load h offset)

    const int row0 = 2 * tr;
    const int col0 = 4 * tc;
    const int oc0  = 8 * tc;

    for (int half = 0; half < 2; ++half) {
        const int it = (half == 0) ? (63 - pair) : pair;   // q-tile index

        __syncthreads();
        {
            const float* src = g_K + ((size_t)(b * TT) + it * 64) * HH;
            #pragma unroll
            for (int h0 = 0; h0 < 128; h0 += 32) {
                float4 v = *(const float4*)(src + (size_t)ldr * HH + h0 + ldh);
                const int h = h0 + ldh;
                Kt[(h + 0) * 68 + ldr] = v.x;
                Kt[(h + 1) * 68 + ldr] = v.y;
                Kt[(h + 2) * 68 + ldr] = v.z;
                Kt[(h + 3) * 68 + ldr] = v.w;
            }
        }

        float m[2] = {-1e30f, -1e30f};
        float l[2] = {0.f, 0.f};
        float O[2][8];
        #pragma unroll
        for (int i = 0; i < 2; ++i)
            #pragma unroll
            for (int j = 0; j < 8; ++j) O[i][j] = 0.f;

        for (int j = 0; j <= it; ++j) {
            __syncthreads();
            {
                const float* qsrc = g_Q + ((size_t)(b * TT) + j * 64) * HH;
                #pragma unroll
                for (int h0 = 0; h0 < 128; h0 += 32) {
                    float4 v = *(const float4*)(qsrc + (size_t)ldr * HH + h0 + ldh);
                    const int h = h0 + ldh;
                    Qt[(h + 0) * 68 + ldr] = v.x;
                    Qt[(h + 1) * 68 + ldr] = v.y;
                    Qt[(h + 2) * 68 + ldr] = v.z;
                    Qt[(h + 3) * 68 + ldr] = v.w;
                }
                const float* vsrc = g_V + ((size_t)(b * TT) + j * 64) * HH;
                int f4 = tid;
                #pragma unroll
                for (int v4 = 0; v4 < 4; ++v4, f4 += 512) {
                    const int vr = f4 >> 5;
                    const int vh = (f4 & 31) << 2;
                    *(float4*)&sV[vr * 128 + vh] =
                        *(const float4*)(vsrc + (size_t)vr * HH + vh);
                }
            }
            __syncthreads();

            float S[2][4];
            #pragma unroll
            for (int i = 0; i < 2; ++i)
                #pragma unroll
                for (int jj = 0; jj < 4; ++jj) S[i][jj] = 0.f;

            #pragma unroll 8
            for (int kk = 0; kk < 128; ++kk) {
                float2 a = *(float2*)&Kt[kk * 68 + row0];
                float4 q = *(float4*)&Qt[kk * 68 + col0];
                S[0][0] = fmaf(a.x, q.x, S[0][0]);
                S[0][1] = fmaf(a.x, q.y, S[0][1]);
                S[0][2] = fmaf(a.x, q.z, S[0][2]);
                S[0][3] = fmaf(a.x, q.w, S[0][3]);
                S[1][0] = fmaf(a.y, q.x, S[1][0]);
                S[1][1] = fmaf(a.y, q.y, S[1][1]);
                S[1][2] = fmaf(a.y, q.z, S[1][2]);
                S[1][3] = fmaf(a.y, q.w, S[1][3]);
            }

            const bool diag = (j == it);
            #pragma unroll
            for (int i = 0; i < 2; ++i)
                #pragma unroll
                for (int jj = 0; jj < 4; ++jj) {
                    float v = S[i][jj] * 0.03125f;   // C^-0.5 = 1/32
                    if (diag && (col0 + jj > row0 + i)) v = -1e30f;
                    S[i][jj] = v;
                }

            #pragma unroll
            for (int i = 0; i < 2; ++i) {
                float rmax = fmaxf(fmaxf(S[i][0], S[i][1]), fmaxf(S[i][2], S[i][3]));
                #pragma unroll
                for (int off = 8; off >= 1; off >>= 1)
                    rmax = fmaxf(rmax, __shfl_xor_sync(0xffffffffu, rmax, off));
                const float mnew = fmaxf(m[i], rmax);
                const float corr = __expf(m[i] - mnew);
                float rsum = 0.f;
                #pragma unroll
                for (int jj = 0; jj < 4; ++jj) {
                    S[i][jj] = __expf(S[i][jj] - mnew);
                    rsum += S[i][jj];
                }
                #pragma unroll
                for (int off = 8; off >= 1; off >>= 1)
                    rsum += __shfl_xor_sync(0xffffffffu, rsum, off);
                l[i] = l[i] * corr + rsum;
                m[i] = mnew;
                #pragma unroll
                for (int jj = 0; jj < 8; ++jj) O[i][jj] *= corr;
                float4 p4 = {S[i][0], S[i][1], S[i][2], S[i][3]};
                *(float4*)&sP[(row0 + i) * 68 + col0] = p4;
            }
            __syncthreads();

            const float* __restrict__ pr0 = &sP[(row0 + 0) * 68];
            const float* __restrict__ pr1 = &sP[(row0 + 1) * 68];
            #pragma unroll 4
            for (int c = 0; c < 64; ++c) {
                const float p0 = pr0[c];
                const float p1 = pr1[c];
                float4 v0 = *(const float4*)&sV[c * 128 + oc0];
                float4 v1 = *(const float4*)&sV[c * 128 + oc0 + 4];
                O[0][0] = fmaf(p0, v0.x, O[0][0]);
                O[0][1] = fmaf(p0, v0.y, O[0][1]);
                O[0][2] = fmaf(p0, v0.z, O[0][2]);
                O[0][3] = fmaf(p0, v0.w, O[0][3]);
                O[0][4] = fmaf(p0, v1.x, O[0][4]);
                O[0][5] = fmaf(p0, v1.y, O[0][5]);
                O[0][6] = fmaf(p0, v1.z, O[0][6]);
                O[0][7] = fmaf(p0, v1.w, O[0][7]);
                O[1][0] = fmaf(p1, v0.x, O[1][0]);
                O[1][1] = fmaf(p1, v0.y, O[1][1]);
                O[1][2] = fmaf(p1, v0.z, O[1][2]);
                O[1][3] = fmaf(p1, v0.w, O[1][3]);
                O[1][4] = fmaf(p1, v1.x, O[1][4]);
                O[1][5] = fmaf(p1, v1.y, O[1][5]);
                O[1][6] = fmaf(p1, v1.z, O[1][6]);
                O[1][7] = fmaf(p1, v1.w, O[1][7]);
            }
        }

        float* ob = out + ((size_t)(b * TT) + it * 64) * HH;
        #pragma unroll
        for (int i = 0; i < 2; ++i) {
            const float linv = 1.f / l[i];
            float4 o0 = {O[i][0] * linv, O[i][1] * linv, O[i][2] * linv, O[i][3] * linv};
            float4 o1 = {O[i][4] * linv, O[i][5] * linv, O[i][6] * linv, O[i][7] * linv};
            *(float4*)&ob[(2 * tr + i) * HH + oc0]     = o0;
            *(float4*)&ob[(2 * tr + i) * HH + oc0 + 4] = o1;
        }
    }
}

// ---------------------------------------------------------------------------
// Launch
// ---------------------------------------------------------------------------
extern "C" void kernel_launch(void* const* d_in, const int* in_sizes, int n_in,
                              void* d_out, int out_size)
{
    const float* ix = (const float*)d_in[0];
    const float* Wq = (const float*)d_in[1];
    const float* Wk = (const float*)d_in[2];
    const float* Wv = (const float*)d_in[3];
    float* out = (float*)d_out;

    // 1. Split inputs to bf16 hi/lo
    convert_a<<<(BB * TT * CC) / (256 * 4), 256>>>(ix);
    transpose_w<<<dim3((HH * CC) / 256, 3), 256>>>(Wq, Wk, Wv);

    // 2. HMMA (mma.sync) projection GEMMs
    cudaFuncSetAttribute(gemm_proj, cudaFuncAttributeMaxDynamicSharedMemorySize,
                         GEMM_SMEM);
    gemm_proj<<<dim3(128, 3), 256, GEMM_SMEM>>>();

    // 3. Attention (fp32 FFMA, unchanged)
    const size_t shmem = (size_t)(128 * 68 * 2 + 64 * 128 + 64 * 68) * sizeof(float);
    cudaFuncSetAttribute(attn_kernel, cudaFuncAttributeMaxDynamicSharedMemorySize,
                         (int)shmem);
    attn_kernel<<<dim3(32, 4), 512, shmem>>>(out);
}

// round 7
// speedup vs baseline: 2.9013x; 2.3727x over previous
#include <cuda_runtime.h>
#include <cuda_bf16.h>
#include <cstdint>

// Problem constants
#define BB 4
#define TT 4096
#define CC 1024
#define HH 128

// ---------------------------------------------------------------------------
// Device scratch (no allocations allowed). Q/K/V live ONLY as split bf16.
// ---------------------------------------------------------------------------
__device__ __nv_bfloat16 g_Qhi[BB * TT * HH];
__device__ __nv_bfloat16 g_Qlo[BB * TT * HH];
__device__ __nv_bfloat16 g_Khi[BB * TT * HH];
__device__ __nv_bfloat16 g_Klo[BB * TT * HH];
__device__ __nv_bfloat16 g_Vhi[BB * TT * HH];
__device__ __nv_bfloat16 g_Vlo[BB * TT * HH];
__device__ __nv_bfloat16 g_Ahi[BB * TT * CC];       // ix split-hi  [16384][1024]
__device__ __nv_bfloat16 g_Alo[BB * TT * CC];       // ix split-lo
__device__ __nv_bfloat16 g_Bhi[3 * HH * CC];        // W^T split-hi [3][128][1024]
__device__ __nv_bfloat16 g_Blo[3 * HH * CC];        // W^T split-lo

// ---------------------------------------------------------------------------
// Helpers (baseline sm_100 PTX only: ldmatrix + mma.sync)
// ---------------------------------------------------------------------------
__device__ __forceinline__ uint32_t smem_u32(const void* p) {
    uint32_t a;
    asm("{ .reg .u64 t; cvta.to.shared.u64 t, %1; cvt.u32.u64 %0, t; }"
        : "=r"(a) : "l"(p));
    return a;
}

#define LDMX4(r, addr) \
    asm volatile("ldmatrix.sync.aligned.m8n8.x4.shared.b16 {%0,%1,%2,%3}, [%4];" \
        : "=r"((r)[0]), "=r"((r)[1]), "=r"((r)[2]), "=r"((r)[3]) : "r"(addr))

#define LDMX4T(r, addr) \
    asm volatile("ldmatrix.sync.aligned.m8n8.x4.trans.shared.b16 {%0,%1,%2,%3}, [%4];" \
        : "=r"((r)[0]), "=r"((r)[1]), "=r"((r)[2]), "=r"((r)[3]) : "r"(addr))

#define MMA_BF16(c, a, b0, b1) \
    asm volatile("mma.sync.aligned.m16n8k16.row.col.f32.bf16.bf16.f32 " \
        "{%0,%1,%2,%3}, {%4,%5,%6,%7}, {%8,%9}, {%0,%1,%2,%3};" \
        : "+f"((c)[0]), "+f"((c)[1]), "+f"((c)[2]), "+f"((c)[3]) \
        : "r"((a)[0]), "r"((a)[1]), "r"((a)[2]), "r"((a)[3]), "r"(b0), "r"(b1))

__device__ __forceinline__ uint32_t pack_bf2(__nv_bfloat16 a, __nv_bfloat16 b) {
    return (uint32_t)__bfloat16_as_ushort(a) |
           ((uint32_t)__bfloat16_as_ushort(b) << 16);
}
__device__ __forceinline__ void split2(float a, float b, uint32_t& hi, uint32_t& lo) {
    __nv_bfloat16 h0 = __float2bfloat16(a), h1 = __float2bfloat16(b);
    hi = pack_bf2(h0, h1);
    lo = pack_bf2(__float2bfloat16(a - __bfloat162float(h0)),
                  __float2bfloat16(b - __bfloat162float(h1)));
}

// ---------------------------------------------------------------------------
// Split ix -> (hi, lo) bf16. 16.8M elems, 4/thread. Memory-bound.
// ---------------------------------------------------------------------------
__global__ __launch_bounds__(256) void convert_a(const float* __restrict__ x)
{
    const size_t base = ((size_t)blockIdx.x * 256 + threadIdx.x) * 4;
    float4 v = *(const float4*)(x + base);
    uint2 ph, pl;
    split2(v.x, v.y, ph.x, pl.x);
    split2(v.z, v.w, ph.y, pl.y);
    *(uint2*)&g_Ahi[base] = ph;
    *(uint2*)&g_Alo[base] = pl;
}

// ---------------------------------------------------------------------------
// Transpose + split W [1024,128] -> W^T [128,1024] bf16 hi/lo.
// ---------------------------------------------------------------------------
__global__ __launch_bounds__(256) void transpose_w(
    const float* __restrict__ Wq, const float* __restrict__ Wk,
    const float* __restrict__ Wv)
{
    const int w = blockIdx.y;
    const float* src = (w == 0) ? Wq : (w == 1) ? Wk : Wv;
    const int idx = blockIdx.x * 256 + threadIdx.x;   // 0..131071
    const int n = idx >> 10;
    const int k = idx & 1023;
    const float v = src[(size_t)k * HH + n];
    __nv_bfloat16 h = __float2bfloat16(v);
    g_Bhi[(size_t)w * HH * CC + idx] = h;
    g_Blo[(size_t)w * HH * CC + idx] = __float2bfloat16(v - __bfloat162float(h));
}

// ---------------------------------------------------------------------------
// HMMA projection GEMM: D[128,128] = A[128,1024] @ B^T, split-bf16 (3 passes).
// Epilogue writes Q/K/V directly as split bf16 hi/lo.
// ---------------------------------------------------------------------------
#define PADK       40                     // 32 k elems + 8 pad
#define TILE_BYTES (128 * PADK * 2)
#define BUF_BYTES  (4 * TILE_BYTES)
#define GEMM_SMEM  (2 * BUF_BYTES)

__global__ __launch_bounds__(256) void gemm_proj()
{
    extern __shared__ __align__(16) char smem[];
    const uint32_t sb = smem_u32(smem);
    const int tid  = threadIdx.x;
    const int w    = tid >> 5;
    const int lane = tid & 31;
    const int mt   = blockIdx.x;
    const int wt   = blockIdx.y;

    const __nv_bfloat16* Ah = g_Ahi;
    const __nv_bfloat16* Al = g_Alo;
    const __nv_bfloat16* Bh = g_Bhi + (size_t)wt * HH * CC;
    const __nv_bfloat16* Bl = g_Blo + (size_t)wt * HH * CC;
    __nv_bfloat16* Oh = (wt == 0) ? g_Qhi : (wt == 1) ? g_Khi : g_Vhi;
    __nv_bfloat16* Ol = (wt == 0) ? g_Qlo : (wt == 1) ? g_Klo : g_Vlo;

    const size_t arow0 = (size_t)mt * 128;

    float acc[16][4];
    #pragma unroll
    for (int i = 0; i < 16; ++i)
        #pragma unroll
        for (int j = 0; j < 4; ++j) acc[i][j] = 0.f;

    auto ld_stage = [&](int s) {
        const uint32_t buf = (uint32_t)(s & 1) * BUF_BYTES;
        const int k0 = s * 32;
        #pragma unroll
        for (int h = 0; h < 2; ++h) {
            const int c   = tid + h * 256;
            const int row = c >> 2;
            const int ke  = (c & 3) * 8;
            const uint32_t so = buf + (uint32_t)(row * PADK + ke) * 2;
            *(uint4*)(smem + so)                  = *(const uint4*)(Ah + (arow0 + row) * CC + k0 + ke);
            *(uint4*)(smem + so + TILE_BYTES)     = *(const uint4*)(Al + (arow0 + row) * CC + k0 + ke);
            *(uint4*)(smem + so + 2 * TILE_BYTES) = *(const uint4*)(Bh + (size_t)row * CC + k0 + ke);
            *(uint4*)(smem + so + 3 * TILE_BYTES) = *(const uint4*)(Bl + (size_t)row * CC + k0 + ke);
        }
    };

    const int lrow  = lane & 15;
    const int lcol8 = (lane >> 4) * 8;

    ld_stage(0);
    __syncthreads();

    for (int s = 0; s < 32; ++s) {
        if (s + 1 < 32) ld_stage(s + 1);
        const uint32_t buf = sb + (uint32_t)(s & 1) * BUF_BYTES;
        #pragma unroll
        for (int kk = 0; kk < 32; kk += 16) {
            const uint32_t aaddr =
                buf + (uint32_t)((16 * w + lrow) * PADK + kk + lcol8) * 2;
            uint32_t ah[4], al[4];
            LDMX4(ah, aaddr);
            LDMX4(al, aaddr + TILE_BYTES);
            #pragma unroll
            for (int j = 0; j < 8; ++j) {
                const uint32_t baddr = buf + 2 * TILE_BYTES +
                    (uint32_t)((16 * j + lrow) * PADK + kk + lcol8) * 2;
                uint32_t bh[4], bl[4];
                LDMX4(bh, baddr);
                LDMX4(bl, baddr + TILE_BYTES);
                MMA_BF16(acc[2 * j],     ah, bh[0], bh[2]);
                MMA_BF16(acc[2 * j],     ah, bl[0], bl[2]);
                MMA_BF16(acc[2 * j],     al, bh[0], bh[2]);
                MMA_BF16(acc[2 * j + 1], ah, bh[1], bh[3]);
                MMA_BF16(acc[2 * j + 1], ah, bl[1], bl[3]);
                MMA_BF16(acc[2 * j + 1], al, bh[1], bh[3]);
            }
        }
        __syncthreads();
    }

    const int m0 = 16 * w + (lane >> 2);
    const int nc = (lane & 3) * 2;
    #pragma unroll
    for (int nt = 0; nt < 16; ++nt) {
        uint32_t hi, lo;
        split2(acc[nt][0], acc[nt][1], hi, lo);
        *(uint32_t*)&Oh[(arow0 + m0) * HH + nt * 8 + nc] = hi;
        *(uint32_t*)&Ol[(arow0 + m0) * HH + nt * 8 + nc] = lo;
        split2(acc[nt][2], acc[nt][3], hi, lo);
        *(uint32_t*)&Oh[(arow0 + m0 + 8) * HH + nt * 8 + nc] = hi;
        *(uint32_t*)&Ol[(arow0 + m0 + 8) * HH + nt * 8 + nc] = lo;
    }
}

// ---------------------------------------------------------------------------
// HMMA flash attention. scores[t,s] = k[t]·q[s]/32, s <= t.
// 256 thr / 8 warps. Tiles 64(t) x 64(s), D=128.
// S: warps = 4 row-groups x 2 col-groups; split-bf16, 3 MMA passes.
// PV: warps = 4 row-groups x 2 h-groups; P hi/lo via smem, V^T via ldmatrix.trans.
// Pairing: block p does t-tiles {63-p, p} -> 65 s-tiles each; grid (32,4).
// ---------------------------------------------------------------------------
#define PADL 136                       // K/Q/V smem row stride (bf16 elems)
#define PADP 72                        // P smem row stride
#define E_KH 0
#define E_KL 8704
#define E_QH 17408
#define E_QL 26112
#define E_VH 34816
#define E_VL 43520
#define E_PH 52224
#define E_PL 56832
#define RED_BYTE 122880                // 61440 bf16 elems * 2
#define ATT_SMEM (RED_BYTE + 448 * 4)

__global__ __launch_bounds__(256) void attn_kernel(float* __restrict__ out)
{
    extern __shared__ __align__(16) char sm[];
    float* rmax2  = (float*)(sm + RED_BYTE);   // [64][2]
    float* rsum2  = rmax2 + 128;               // [64][2]
    float* m_s    = rsum2 + 128;               // [64]
    float* l_s    = m_s + 64;                  // [64]
    float* corr_s = l_s + 64;                  // [64]
    const uint32_t sb = smem_u32(sm);

    const int b    = blockIdx.y;
    const int pair = blockIdx.x;
    const int tid  = threadIdx.x;
    const int lane = tid & 31;
    const int wid  = tid >> 5;
    const int wr   = wid & 3;           // row group: rows 16*wr..16*wr+15
    const int wc   = wid >> 2;          // col/h group

    const size_t bo = (size_t)b * TT * HH;
    const __nv_bfloat16* Qh = g_Qhi + bo;
    const __nv_bfloat16* Ql = g_Qlo + bo;
    const __nv_bfloat16* Kh = g_Khi + bo;
    const __nv_bfloat16* Kl = g_Klo + bo;
    const __nv_bfloat16* Vh = g_Vhi + bo;
    const __nv_bfloat16* Vl = g_Vlo + bo;

    // copy one 64x128 bf16 tile (row stride 128) into smem (stride PADL)
    auto cp_tile = [&](uint32_t dstE, const __nv_bfloat16* src) {
        #pragma unroll
        for (int h = 0; h < 4; ++h) {
            const int c = tid + h * 256;            // 0..1023
            const int row = c >> 4, ch = (c & 15) * 8;
            *(uint4*)(sm + (uint32_t)(dstE + row * PADL + ch) * 2) =
                *(const uint4*)(src + row * HH + ch);
        }
    };

    const int lrow  = lane & 15;
    const int lcol8 = (lane >> 4) * 8;
    const int r1    = 16 * wr + (lane >> 2);   // local row (0..63); also r1+8
    const int cpair = (lane & 3) * 2;

    for (int half = 0; half < 2; ++half) {
        const int it = (half == 0) ? (63 - pair) : pair;
        const int t0 = it * 64;

        __syncthreads();                 // prior half fully done with smem
        cp_tile(E_KH, Kh + (size_t)t0 * HH);
        cp_tile(E_KL, Kl + (size_t)t0 * HH);
        if (tid < 64) { m_s[tid] = -1e30f; l_s[tid] = 0.f; }

        float accO[8][4];
        #pragma unroll
        for (int i = 0; i < 8; ++i)
            #pragma unroll
            for (int j = 0; j < 4; ++j) accO[i][j] = 0.f;

        for (int j = 0; j <= it; ++j) {
            const int s0 = j * 64;
            __syncthreads();             // prev PV done reading sQ/sV/sP (and K ready)
            cp_tile(E_QH, Qh + (size_t)s0 * HH);
            cp_tile(E_QL, Ql + (size_t)s0 * HH);
            cp_tile(E_VH, Vh + (size_t)s0 * HH);
            cp_tile(E_VL, Vl + (size_t)s0 * HH);
            __syncthreads();

            // ---- S = K @ Q^T (rows 16*wr.., cols 32*wc..), split-bf16 ----
            float accS[4][4];
            #pragma unroll
            for (int i = 0; i < 4; ++i)
                #pragma unroll
                for (int jj = 0; jj < 4; ++jj) accS[i][jj] = 0.f;

            #pragma unroll
            for (int kk = 0; kk < 128; kk += 16) {
                const uint32_t ka = sb +
                    (uint32_t)((16 * wr + lrow) * PADL + kk + lcol8) * 2;
                uint32_t ah[4], al[4];
                LDMX4(ah, ka + E_KH * 2);
                LDMX4(al, ka + E_KL * 2);
                #pragma unroll
                for (int n2 = 0; n2 < 2; ++n2) {
                    const uint32_t qa = sb +
                        (uint32_t)((32 * wc + 16 * n2 + lrow) * PADL + kk + lcol8) * 2;
                    uint32_t bh[4], bl[4];
                    LDMX4(bh, qa + E_QH * 2);
                    LDMX4(bl, qa + E_QL * 2);
                    MMA_BF16(accS[2 * n2],     ah, bh[0], bh[2]);
                    MMA_BF16(accS[2 * n2],     ah, bl[0], bl[2]);
                    MMA_BF16(accS[2 * n2],     al, bh[0], bh[2]);
                    MMA_BF16(accS[2 * n2 + 1], ah, bh[1], bh[3]);
                    MMA_BF16(accS[2 * n2 + 1], ah, bl[1], bl[3]);
                    MMA_BF16(accS[2 * n2 + 1], al, bh[1], bh[3]);
                }
            }

            // ---- scale + causal mask ----
            const bool diag = (j == it);
            #pragma unroll
            for (int nt = 0; nt < 4; ++nt)
                #pragma unroll
                for (int e = 0; e < 2; ++e) {
                    const int col = 32 * wc + nt * 8 + cpair + e;
                    float v0 = accS[nt][e]     * 0.03125f;
                    float v1 = accS[nt][e + 2] * 0.03125f;
                    if (diag && col > r1)     v0 = -1e30f;
                    if (diag && col > r1 + 8) v1 = -1e30f;
                    accS[nt][e]     = v0;
                    accS[nt][e + 2] = v1;
                }

            // ---- partial row max (this warp's 32 cols) ----
            float pm0 = -1e30f, pm1 = -1e30f;
            #pragma unroll
            for (int nt = 0; nt < 4; ++nt) {
                pm0 = fmaxf(pm0, fmaxf(accS[nt][0], accS[nt][1]));
                pm1 = fmaxf(pm1, fmaxf(accS[nt][2], accS[nt][3]));
            }
            #pragma unroll
            for (int off = 1; off <= 2; off <<= 1) {
                pm0 = fmaxf(pm0, __shfl_xor_sync(0xffffffffu, pm0, off));
                pm1 = fmaxf(pm1, __shfl_xor_sync(0xffffffffu, pm1, off));
            }
            if ((lane & 3) == 0) {
                rmax2[r1 * 2 + wc]       = pm0;
                rmax2[(r1 + 8) * 2 + wc] = pm1;
            }
            __syncthreads();

            // ---- exp + partial sums + store P (bf16 hi/lo) ----
            const float mn0 = fmaxf(m_s[r1],
                                fmaxf(rmax2[r1 * 2], rmax2[r1 * 2 + 1]));
            const float mn1 = fmaxf(m_s[r1 + 8],
                                fmaxf(rmax2[(r1 + 8) * 2], rmax2[(r1 + 8) * 2 + 1]));
            float ps0 = 0.f, ps1 = 0.f;
            #pragma unroll
            for (int nt = 0; nt < 4; ++nt) {
                float p00 = __expf(accS[nt][0] - mn0);
                float p01 = __expf(accS[nt][1] - mn0);
                float p10 = __expf(accS[nt][2] - mn1);
                float p11 = __expf(accS[nt][3] - mn1);
                ps0 += p00 + p01;
                ps1 += p10 + p11;
                uint32_t hi, lo;
                const int col = 32 * wc + nt * 8 + cpair;
                split2(p00, p01, hi, lo);
                *(uint32_t*)(sm + (uint32_t)(E_PH + r1 * PADP + col) * 2) = hi;
                *(uint32_t*)(sm + (uint32_t)(E_PL + r1 * PADP + col) * 2) = lo;
                split2(p10, p11, hi, lo);
                *(uint32_t*)(sm + (uint32_t)(E_PH + (r1 + 8) * PADP + col) * 2) = hi;
                *(uint32_t*)(sm + (uint32_t)(E_PL + (r1 + 8) * PADP + col) * 2) = lo;
            }
            #pragma unroll
            for (int off = 1; off <= 2; off <<= 1) {
                ps0 += __shfl_xor_sync(0xffffffffu, ps0, off);
                ps1 += __shfl_xor_sync(0xffffffffu, ps1, off);
            }
            if ((lane & 3) == 0) {
                rsum2[r1 * 2 + wc]       = ps0;
                rsum2[(r1 + 8) * 2 + wc] = ps1;
            }
            __syncthreads();

            // ---- scalar m/l/corr update ----
            if (tid < 64) {
                const float mold = m_s[tid];
                const float mn = fmaxf(mold, fmaxf(rmax2[tid * 2], rmax2[tid * 2 + 1]));
                const float cr = __expf(mold - mn);
                l_s[tid] = l_s[tid] * cr + rsum2[tid * 2] + rsum2[tid * 2 + 1];
                m_s[tid] = mn;
                corr_s[tid] = cr;
            }
            __syncthreads();

            // ---- O rescale + O += P @ V (warp: rows 16*wr.., h 64*wc..) ----
            const float c0 = corr_s[r1];
            const float c1 = corr_s[r1 + 8];
            #pragma unroll
            for (int nt = 0; nt < 8; ++nt) {
                accO[nt][0] *= c0; accO[nt][1] *= c0;
                accO[nt][2] *= c1; accO[nt][3] *= c1;
            }
            #pragma unroll
            for (int k2 = 0; k2 < 64; k2 += 16) {
                const uint32_t pa = sb +
                    (uint32_t)((16 * wr + lrow) * PADP + k2 + lcol8) * 2;
                uint32_t ph[4], pl[4];
                LDMX4(ph, pa + E_PH * 2);
                LDMX4(pl, pa + E_PL * 2);
                #pragma unroll
                for (int n4 = 0; n4 < 4; ++n4) {
                    const uint32_t va = sb +
                        (uint32_t)((k2 + lrow) * PADL + 64 * wc + n4 * 16 + lcol8) * 2;
                    uint32_t vh[4], vl[4];
                    LDMX4T(vh, va + E_VH * 2);
                    LDMX4T(vl, va + E_VL * 2);
                    MMA_BF16(accO[2 * n4],     ph, vh[0], vh[1]);
                    MMA_BF16(accO[2 * n4],     ph, vl[0], vl[1]);
                    MMA_BF16(accO[2 * n4],     pl, vh[0], vh[1]);
                    MMA_BF16(accO[2 * n4 + 1], ph, vh[2], vh[3]);
                    MMA_BF16(accO[2 * n4 + 1], ph, vl[2], vl[3]);
                    MMA_BF16(accO[2 * n4 + 1], pl, vh[2], vh[3]);
                }
            }
        }

        // ---- epilogue: O / l -> out ----
        const float li0 = 1.f / l_s[r1];
        const float li1 = 1.f / l_s[r1 + 8];
        float* ob = out + ((size_t)b * TT + t0) * HH;
        #pragma unroll
        for (int nt = 0; nt < 8; ++nt) {
            const int h0 = 64 * wc + nt * 8 + cpair;
            float2 o0 = {accO[nt][0] * li0, accO[nt][1] * li0};
            float2 o1 = {accO[nt][2] * li1, accO[nt][3] * li1};
            *(float2*)&ob[(size_t)r1 * HH + h0]       = o0;
            *(float2*)&ob[(size_t)(r1 + 8) * HH + h0] = o1;
        }
    }
}

// ---------------------------------------------------------------------------
// Launch
// ---------------------------------------------------------------------------
extern "C" void kernel_launch(void* const* d_in, const int* in_sizes, int n_in,
                              void* d_out, int out_size)
{
    const float* ix = (const float*)d_in[0];
    const float* Wq = (const float*)d_in[1];
    const float* Wk = (const float*)d_in[2];
    const float* Wv = (const float*)d_in[3];
    float* out = (float*)d_out;

    // 1. Split inputs to bf16 hi/lo
    convert_a<<<(BB * TT * CC) / (256 * 4), 256>>>(ix);
    transpose_w<<<dim3((HH * CC) / 256, 3), 256>>>(Wq, Wk, Wv);

    // 2. HMMA projection GEMMs (emit split-bf16 Q/K/V)
    cudaFuncSetAttribute(gemm_proj, cudaFuncAttributeMaxDynamicSharedMemorySize,
                         GEMM_SMEM);
    gemm_proj<<<dim3(128, 3), 256, GEMM_SMEM>>>();

    // 3. HMMA flash attention (resubmit: round-6 bench was an infra failure)
    cudaFuncSetAttribute(attn_kernel, cudaFuncAttributeMaxDynamicSharedMemorySize,
                         ATT_SMEM);
    attn_kernel<<<dim3(32, 4), 256, ATT_SMEM>>>(out);
}

// round 9
// speedup vs baseline: 3.9305x; 1.3547x over previous
#include <cuda_runtime.h>
#include <cuda_bf16.h>
#include <cstdint>

// Problem constants
#define BB 4
#define TT 4096
#define CC 1024
#define HH 128

// ---------------------------------------------------------------------------
// Device scratch (no allocations allowed). Q/K/V live ONLY as split bf16.
// ---------------------------------------------------------------------------
__device__ __nv_bfloat16 g_Qhi[BB * TT * HH];
__device__ __nv_bfloat16 g_Qlo[BB * TT * HH];
__device__ __nv_bfloat16 g_Khi[BB * TT * HH];
__device__ __nv_bfloat16 g_Klo[BB * TT * HH];
__device__ __nv_bfloat16 g_Vhi[BB * TT * HH];
__device__ __nv_bfloat16 g_Vlo[BB * TT * HH];
__device__ __nv_bfloat16 g_Bhi[3 * HH * CC];        // W^T split-hi [3][128][1024]
__device__ __nv_bfloat16 g_Blo[3 * HH * CC];        // W^T split-lo

// ---------------------------------------------------------------------------
// Helpers (baseline sm_100 PTX: ldmatrix + mma.sync + cp.async)
// ---------------------------------------------------------------------------
__device__ __forceinline__ uint32_t smem_u32(const void* p) {
    uint32_t a;
    asm("{ .reg .u64 t; cvta.to.shared.u64 t, %1; cvt.u32.u64 %0, t; }"
        : "=r"(a) : "l"(p));
    return a;
}

#define LDMX4(r, addr) \
    asm volatile("ldmatrix.sync.aligned.m8n8.x4.shared.b16 {%0,%1,%2,%3}, [%4];" \
        : "=r"((r)[0]), "=r"((r)[1]), "=r"((r)[2]), "=r"((r)[3]) : "r"(addr))

#define LDMX4T(r, addr) \
    asm volatile("ldmatrix.sync.aligned.m8n8.x4.trans.shared.b16 {%0,%1,%2,%3}, [%4];" \
        : "=r"((r)[0]), "=r"((r)[1]), "=r"((r)[2]), "=r"((r)[3]) : "r"(addr))

#define MMA_BF16(c, a, b0, b1) \
    asm volatile("mma.sync.aligned.m16n8k16.row.col.f32.bf16.bf16.f32 " \
        "{%0,%1,%2,%3}, {%4,%5,%6,%7}, {%8,%9}, {%0,%1,%2,%3};" \
        : "+f"((c)[0]), "+f"((c)[1]), "+f"((c)[2]), "+f"((c)[3]) \
        : "r"((a)[0]), "r"((a)[1]), "r"((a)[2]), "r"((a)[3]), "r"(b0), "r"(b1))

#define CP_ASYNC16(saddr, gptr) \
    asm volatile("cp.async.cg.shared.global [%0], [%1], 16;" \
        :: "r"(saddr), "l"(gptr) : "memory")
#define CP_COMMIT() asm volatile("cp.async.commit_group;" ::: "memory")
#define CP_WAIT0()  asm volatile("cp.async.wait_group 0;" ::: "memory")

__device__ __forceinline__ uint32_t pack_bf2(__nv_bfloat16 a, __nv_bfloat16 b) {
    return (uint32_t)__bfloat16_as_ushort(a) |
           ((uint32_t)__bfloat16_as_ushort(b) << 16);
}
__device__ __forceinline__ void split2(float a, float b, uint32_t& hi, uint32_t& lo) {
    __nv_bfloat16 h0 = __float2bfloat16(a), h1 = __float2bfloat16(b);
    hi = pack_bf2(h0, h1);
    lo = pack_bf2(__float2bfloat16(a - __bfloat162float(h0)),
                  __float2bfloat16(b - __bfloat162float(h1)));
}

// ---------------------------------------------------------------------------
// Transpose + split W [1024,128] -> W^T [128,1024] bf16 hi/lo.
// ---------------------------------------------------------------------------
__global__ __launch_bounds__(256) void transpose_w(
    const float* __restrict__ Wq, const float* __restrict__ Wk,
    const float* __restrict__ Wv)
{
    const int w = blockIdx.y;
    const float* src = (w == 0) ? Wq : (w == 1) ? Wk : Wv;
    const int idx = blockIdx.x * 256 + threadIdx.x;   // 0..131071
    const int n = idx >> 10;
    const int k = idx & 1023;
    const float v = src[(size_t)k * HH + n];
    __nv_bfloat16 h = __float2bfloat16(v);
    g_Bhi[(size_t)w * HH * CC + idx] = h;
    g_Blo[(size_t)w * HH * CC + idx] = __float2bfloat16(v - __bfloat162float(h));
}

// ---------------------------------------------------------------------------
// HMMA projection GEMM with FUSED fp32->split-bf16 conversion of X.
// D[128,128] = A[128,1024] @ B^T, split-bf16 (3 passes).
// ld_regs(s+1) -> compute(s) -> st_smem(s+1): LDG latency hidden behind MMAs.
// ---------------------------------------------------------------------------
#define PADK       40                     // 32 k elems + 8 pad
#define TILE_BYTES (128 * PADK * 2)
#define BUF_BYTES  (4 * TILE_BYTES)
#define GEMM_SMEM  (2 * BUF_BYTES)

struct StageRegs {
    float4 xa[2], xb[2];   // 8 fp32 X values per h
    uint4  bh[2], bl[2];   // 8 bf16 Bhi/Blo per h
};

__global__ __launch_bounds__(256) void gemm_proj(const float* __restrict__ X)
{
    extern __shared__ __align__(16) char smem[];
    const uint32_t sb = smem_u32(smem);
    const int tid  = threadIdx.x;
    const int w    = tid >> 5;
    const int lane = tid & 31;
    const int mt   = blockIdx.x;
    const int wt   = blockIdx.y;

    const __nv_bfloat16* Bh = g_Bhi + (size_t)wt * HH * CC;
    const __nv_bfloat16* Bl = g_Blo + (size_t)wt * HH * CC;
    __nv_bfloat16* Oh = (wt == 0) ? g_Qhi : (wt == 1) ? g_Khi : g_Vhi;
    __nv_bfloat16* Ol = (wt == 0) ? g_Qlo : (wt == 1) ? g_Klo : g_Vlo;

    const size_t arow0 = (size_t)mt * 128;

    float acc[16][4];
    #pragma unroll
    for (int i = 0; i < 16; ++i)
        #pragma unroll
        for (int j = 0; j < 4; ++j) acc[i][j] = 0.f;

    auto ld_regs = [&](StageRegs& r, int s) {
        const int k0 = s * 32;
        #pragma unroll
        for (int h = 0; h < 2; ++h) {
            const int c   = tid + h * 256;
            const int row = c >> 2;
            const int ke  = (c & 3) * 8;
            const float* xp = X + (arow0 + row) * CC + k0 + ke;
            r.xa[h] = *(const float4*)xp;
            r.xb[h] = *(const float4*)(xp + 4);
            r.bh[h] = *(const uint4*)(Bh + (size_t)row * CC + k0 + ke);
            r.bl[h] = *(const uint4*)(Bl + (size_t)row * CC + k0 + ke);
        }
    };
    auto st_smem = [&](const StageRegs& r, int buf_i) {
        const uint32_t buf = (uint32_t)buf_i * BUF_BYTES;
        #pragma unroll
        for (int h = 0; h < 2; ++h) {
            const int c   = tid + h * 256;
            const int row = c >> 2;
            const int ke  = (c & 3) * 8;
            const uint32_t so = buf + (uint32_t)(row * PADK + ke) * 2;
            uint4 ahi, alo;
            split2(r.xa[h].x, r.xa[h].y, ahi.x, alo.x);
            split2(r.xa[h].z, r.xa[h].w, ahi.y, alo.y);
            split2(r.xb[h].x, r.xb[h].y, ahi.z, alo.z);
            split2(r.xb[h].z, r.xb[h].w, ahi.w, alo.w);
            *(uint4*)(smem + so)                  = ahi;
            *(uint4*)(smem + so + TILE_BYTES)     = alo;
            *(uint4*)(smem + so + 2 * TILE_BYTES) = r.bh[h];
            *(uint4*)(smem + so + 3 * TILE_BYTES) = r.bl[h];
        }
    };

    const int lrow  = lane & 15;
    const int lcol8 = (lane >> 4) * 8;

    {
        StageRegs r0;
        ld_regs(r0, 0);
        st_smem(r0, 0);
    }
    __syncthreads();

    for (int s = 0; s < 32; ++s) {
        StageRegs nxt;
        if (s + 1 < 32) ld_regs(nxt, s + 1);   // LDGs in flight during compute
        const uint32_t buf = sb + (uint32_t)(s & 1) * BUF_BYTES;
        #pragma unroll
        for (int kk = 0; kk < 32; kk += 16) {
            const uint32_t aaddr =
                buf + (uint32_t)((16 * w + lrow) * PADK + kk + lcol8) * 2;
            uint32_t ah[4], al[4];
            LDMX4(ah, aaddr);
            LDMX4(al, aaddr + TILE_BYTES);
            #pragma unroll
            for (int j = 0; j < 8; ++j) {
                const uint32_t baddr = buf + 2 * TILE_BYTES +
                    (uint32_t)((16 * j + lrow) * PADK + kk + lcol8) * 2;
                uint32_t bh[4], bl[4];
                LDMX4(bh, baddr);
                LDMX4(bl, baddr + TILE_BYTES);
                MMA_BF16(acc[2 * j],     ah, bh[0], bh[2]);
                MMA_BF16(acc[2 * j],     ah, bl[0], bl[2]);
                MMA_BF16(acc[2 * j],     al, bh[0], bh[2]);
                MMA_BF16(acc[2 * j + 1], ah, bh[1], bh[3]);
                MMA_BF16(acc[2 * j + 1], ah, bl[1], bl[3]);
                MMA_BF16(acc[2 * j + 1], al, bh[1], bh[3]);
            }
        }
        if (s + 1 < 32) st_smem(nxt, (s + 1) & 1);  // other buffer: safe pre-sync
        __syncthreads();
    }

    const int m0 = 16 * w + (lane >> 2);
    const int nc = (lane & 3) * 2;
    #pragma unroll
    for (int nt = 0; nt < 16; ++nt) {
        uint32_t hi, lo;
        split2(acc[nt][0], acc[nt][1], hi, lo);
        *(uint32_t*)&Oh[(arow0 + m0) * HH + nt * 8 + nc] = hi;
        *(uint32_t*)&Ol[(arow0 + m0) * HH + nt * 8 + nc] = lo;
        split2(acc[nt][2], acc[nt][3], hi, lo);
        *(uint32_t*)&Oh[(arow0 + m0 + 8) * HH + nt * 8 + nc] = hi;
        *(uint32_t*)&Ol[(arow0 + m0 + 8) * HH + nt * 8 + nc] = lo;
    }
}

// ---------------------------------------------------------------------------
// HMMA flash attention, cp.async double-buffered Q/V, 3 barriers/iter.
// scores[t,s] = k[t]·q[s]/32, s <= t. 256 thr / 8 warps, 64x64 tiles, D=128.
// m/l softmax state in registers (redundant across the 8 owners of each row).
// Pairing: block p does t-tiles {63-p, p} -> 65 s-tiles each; grid (32,4).
// (Resubmit: round-8 bench was a broker-side failure; audit found no defect.)
// ---------------------------------------------------------------------------
#define PADL 136
#define PADP 72
#define E_KH 0
#define E_KL 8704
#define E_QH0 17408
#define E_QL0 26112
#define E_VH0 34816
#define E_VL0 43520
#define BUF_STRIDE 34816               // elems between QV buffer 0 and 1
#define E_PH 87040
#define E_PL 91648
#define RED_BYTE 192512                // 96256 elems * 2
#define ATT_SMEM (RED_BYTE + 256 * 4)

__global__ __launch_bounds__(256) void attn_kernel(float* __restrict__ out)
{
    extern __shared__ __align__(16) char sm[];
    float* rmax2 = (float*)(sm + RED_BYTE);   // [64][2]
    float* rsum2 = rmax2 + 128;               // [64][2]
    const uint32_t sb = smem_u32(sm);

    const int b    = blockIdx.y;
    const int pair = blockIdx.x;
    const int tid  = threadIdx.x;
    const int lane = tid & 31;
    const int wid  = tid >> 5;
    const int wr   = wid & 3;           // row group: rows 16*wr..16*wr+15
    const int wc   = wid >> 2;          // col/h group

    const size_t bo = (size_t)b * TT * HH;
    const __nv_bfloat16* Qh = g_Qhi + bo;
    const __nv_bfloat16* Ql = g_Qlo + bo;
    const __nv_bfloat16* Kh = g_Khi + bo;
    const __nv_bfloat16* Kl = g_Klo + bo;
    const __nv_bfloat16* Vh = g_Vhi + bo;
    const __nv_bfloat16* Vl = g_Vlo + bo;

    // async-copy one 64x128 bf16 tile into smem (stride PADL)
    auto cp_tile = [&](uint32_t dstE, const __nv_bfloat16* src) {
        #pragma unroll
        for (int h = 0; h < 4; ++h) {
            const int c = tid + h * 256;            // 0..1023
            const int row = c >> 4, ch = (c & 15) * 8;
            CP_ASYNC16(sb + (uint32_t)(dstE + row * PADL + ch) * 2,
                       src + row * HH + ch);
        }
    };

    const int lrow  = lane & 15;
    const int lcol8 = (lane >> 4) * 8;
    const int r1    = 16 * wr + (lane >> 2);   // local row (0..63); also r1+8
    const int cpair = (lane & 3) * 2;

    for (int half = 0; half < 2; ++half) {
        const int it = (half == 0) ? (63 - pair) : pair;
        const int t0 = it * 64;

        __syncthreads();                 // prior half fully done with smem
        cp_tile(E_KH, Kh + (size_t)t0 * HH);
        cp_tile(E_KL, Kl + (size_t)t0 * HH);
        cp_tile(E_QH0, Qh);              // j=0 tile (s0 = 0)
        cp_tile(E_QL0, Ql);
        cp_tile(E_VH0, Vh);
        cp_tile(E_VL0, Vl);
        CP_COMMIT();

        float m0 = -1e30f, m1 = -1e30f, l0 = 0.f, l1 = 0.f;
        float accO[8][4];
        #pragma unroll
        for (int i = 0; i < 8; ++i)
            #pragma unroll
            for (int j = 0; j < 4; ++j) accO[i][j] = 0.f;

        for (int j = 0; j <= it; ++j) {
            const uint32_t buf = (uint32_t)(j & 1) * BUF_STRIDE;
            CP_WAIT0();
            __syncthreads();             // tiles visible; all warps past PV(j-1)

            if (j < it) {                // prefetch j+1 into other buffer
                const size_t s1 = (size_t)(j + 1) * 64 * HH;
                const uint32_t nb = (uint32_t)((j + 1) & 1) * BUF_STRIDE;
                cp_tile(E_QH0 + nb, Qh + s1);
                cp_tile(E_QL0 + nb, Ql + s1);
                cp_tile(E_VH0 + nb, Vh + s1);
                cp_tile(E_VL0 + nb, Vl + s1);
                CP_COMMIT();
            }

            // ---- S = K @ Q^T (rows 16*wr.., cols 32*wc..), split-bf16 ----
            float accS[4][4];
            #pragma unroll
            for (int i = 0; i < 4; ++i)
                #pragma unroll
                for (int jj = 0; jj < 4; ++jj) accS[i][jj] = 0.f;

            #pragma unroll
            for (int kk = 0; kk < 128; kk += 16) {
                const uint32_t ka = sb +
                    (uint32_t)((16 * wr + lrow) * PADL + kk + lcol8) * 2;
                uint32_t ah[4], al[4];
                LDMX4(ah, ka + E_KH * 2);
                LDMX4(al, ka + E_KL * 2);
                #pragma unroll
                for (int n2 = 0; n2 < 2; ++n2) {
                    const uint32_t qa = sb +
                        (uint32_t)(buf + (32 * wc + 16 * n2 + lrow) * PADL + kk + lcol8) * 2;
                    uint32_t bh[4], bl[4];
                    LDMX4(bh, qa + E_QH0 * 2);
                    LDMX4(bl, qa + E_QL0 * 2);
                    MMA_BF16(accS[2 * n2],     ah, bh[0], bh[2]);
                    MMA_BF16(accS[2 * n2],     ah, bl[0], bl[2]);
                    MMA_BF16(accS[2 * n2],     al, bh[0], bh[2]);
                    MMA_BF16(accS[2 * n2 + 1], ah, bh[1], bh[3]);
                    MMA_BF16(accS[2 * n2 + 1], ah, bl[1], bl[3]);
                    MMA_BF16(accS[2 * n2 + 1], al, bh[1], bh[3]);
                }
            }

            // ---- scale + causal mask ----
            const bool diag = (j == it);
            #pragma unroll
            for (int nt = 0; nt < 4; ++nt)
                #pragma unroll
                for (int e = 0; e < 2; ++e) {
                    const int col = 32 * wc + nt * 8 + cpair + e;
                    float v0 = accS[nt][e]     * 0.03125f;
                    float v1 = accS[nt][e + 2] * 0.03125f;
                    if (diag && col > r1)     v0 = -1e30f;
                    if (diag && col > r1 + 8) v1 = -1e30f;
                    accS[nt][e]     = v0;
                    accS[nt][e + 2] = v1;
                }

            // ---- partial row max (this warp's 32 cols) ----
            float pm0 = -1e30f, pm1 = -1e30f;
            #pragma unroll
            for (int nt = 0; nt < 4; ++nt) {
                pm0 = fmaxf(pm0, fmaxf(accS[nt][0], accS[nt][1]));
                pm1 = fmaxf(pm1, fmaxf(accS[nt][2], accS[nt][3]));
            }
            #pragma unroll
            for (int off = 1; off <= 2; off <<= 1) {
                pm0 = fmaxf(pm0, __shfl_xor_sync(0xffffffffu, pm0, off));
                pm1 = fmaxf(pm1, __shfl_xor_sync(0xffffffffu, pm1, off));
            }
            if ((lane & 3) == 0) {
                rmax2[r1 * 2 + wc]       = pm0;
                rmax2[(r1 + 8) * 2 + wc] = pm1;
            }
            __syncthreads();

            // ---- exp + partial sums + store P (bf16 hi/lo) ----
            const float mn0 = fmaxf(m0, fmaxf(rmax2[r1 * 2], rmax2[r1 * 2 + 1]));
            const float mn1 = fmaxf(m1, fmaxf(rmax2[(r1 + 8) * 2], rmax2[(r1 + 8) * 2 + 1]));
            float ps0 = 0.f, ps1 = 0.f;
            #pragma unroll
            for (int nt = 0; nt < 4; ++nt) {
                float p00 = __expf(accS[nt][0] - mn0);
                float p01 = __expf(accS[nt][1] - mn0);
                float p10 = __expf(accS[nt][2] - mn1);
                float p11 = __expf(accS[nt][3] - mn1);
                ps0 += p00 + p01;
                ps1 += p10 + p11;
                uint32_t hi, lo;
                const int col = 32 * wc + nt * 8 + cpair;
                split2(p00, p01, hi, lo);
                *(uint32_t*)(sm + (uint32_t)(E_PH + r1 * PADP + col) * 2) = hi;
                *(uint32_t*)(sm + (uint32_t)(E_PL + r1 * PADP + col) * 2) = lo;
                split2(p10, p11, hi, lo);
                *(uint32_t*)(sm + (uint32_t)(E_PH + (r1 + 8) * PADP + col) * 2) = hi;
                *(uint32_t*)(sm + (uint32_t)(E_PL + (r1 + 8) * PADP + col) * 2) = lo;
            }
            #pragma unroll
            for (int off = 1; off <= 2; off <<= 1) {
                ps0 += __shfl_xor_sync(0xffffffffu, ps0, off);
                ps1 += __shfl_xor_sync(0xffffffffu, ps1, off);
            }
            if ((lane & 3) == 0) {
                rsum2[r1 * 2 + wc]       = ps0;
                rsum2[(r1 + 8) * 2 + wc] = ps1;
            }
            __syncthreads();

            // ---- register m/l update (redundant across row owners) ----
            const float c0 = __expf(m0 - mn0);
            const float c1 = __expf(m1 - mn1);
            l0 = l0 * c0 + rsum2[r1 * 2] + rsum2[r1 * 2 + 1];
            l1 = l1 * c1 + rsum2[(r1 + 8) * 2] + rsum2[(r1 + 8) * 2 + 1];
            m0 = mn0;
            m1 = mn1;

            // ---- O rescale + O += P @ V ----
            #pragma unroll
            for (int nt = 0; nt < 8; ++nt) {
                accO[nt][0] *= c0; accO[nt][1] *= c0;
                accO[nt][2] *= c1; accO[nt][3] *= c1;
            }
            #pragma unroll
            for (int k2 = 0; k2 < 64; k2 += 16) {
                const uint32_t pa = sb +
                    (uint32_t)((16 * wr + lrow) * PADP + k2 + lcol8) * 2;
                uint32_t ph[4], pl[4];
                LDMX4(ph, pa + E_PH * 2);
                LDMX4(pl, pa + E_PL * 2);
                #pragma unroll
                for (int n4 = 0; n4 < 4; ++n4) {
                    const uint32_t va = sb +
                        (uint32_t)(buf + (k2 + lrow) * PADL + 64 * wc + n4 * 16 + lcol8) * 2;
                    uint32_t vh[4], vl[4];
                    LDMX4T(vh, va + E_VH0 * 2);
                    LDMX4T(vl, va + E_VL0 * 2);
                    MMA_BF16(accO[2 * n4],     ph, vh[0], vh[1]);
                    MMA_BF16(accO[2 * n4],     ph, vl[0], vl[1]);
                    MMA_BF16(accO[2 * n4],     pl, vh[0], vh[1]);
                    MMA_BF16(accO[2 * n4 + 1], ph, vh[2], vh[3]);
                    MMA_BF16(accO[2 * n4 + 1], ph, vl[2], vl[3]);
                    MMA_BF16(accO[2 * n4 + 1], pl, vh[2], vh[3]);
                }
            }
        }

        // ---- epilogue: O / l -> out ----
        const float li0 = 1.f / l0;
        const float li1 = 1.f / l1;
        float* ob = out + ((size_t)b * TT + t0) * HH;
        #pragma unroll
        for (int nt = 0; nt < 8; ++nt) {
            const int h0 = 64 * wc + nt * 8 + cpair;
            float2 o0 = {accO[nt][0] * li0, accO[nt][1] * li0};
            float2 o1 = {accO[nt][2] * li1, accO[nt][3] * li1};
            *(float2*)&ob[(size_t)r1 * HH + h0]       = o0;
            *(float2*)&ob[(size_t)(r1 + 8) * HH + h0] = o1;
        }
    }
}

// ---------------------------------------------------------------------------
// Launch
// ---------------------------------------------------------------------------
extern "C" void kernel_launch(void* const* d_in, const int* in_sizes, int n_in,
                              void* d_out, int out_size)
{
    const float* ix = (const float*)d_in[0];
    const float* Wq = (const float*)d_in[1];
    const float* Wk = (const float*)d_in[2];
    const float* Wv = (const float*)d_in[3];
    float* out = (float*)d_out;

    // 1. Split weights (tiny)
    transpose_w<<<dim3((HH * CC) / 256, 3), 256>>>(Wq, Wk, Wv);

    // 2. HMMA projection GEMMs with fused fp32->split-bf16 conversion
    cudaFuncSetAttribute(gemm_proj, cudaFuncAttributeMaxDynamicSharedMemorySize,
                         GEMM_SMEM);
    gemm_proj<<<dim3(128, 3), 256, GEMM_SMEM>>>(ix);

    // 3. HMMA flash attention, cp.async pipelined
    cudaFuncSetAttribute(attn_kernel, cudaFuncAttributeMaxDynamicSharedMemorySize,
                         ATT_SMEM);
    attn_kernel<<<dim3(32, 4), 256, ATT_SMEM>>>(out);
}